// round 3
// baseline (speedup 1.0000x reference)
#include <cuda_runtime.h>
#include <cuda_bf16.h>

// Fused persistent LSTM decoder for RNN_Decoder_72138270703952 (fp32 + f32x2 FFMA).
// 400 CTAs x 256 threads; each CTA owns 32 rows for the full 16-step recurrence.
// hx/cx in SMEM across steps; W (W_ih at t=0, W_hh after) staged in double-buffered
// SMEM; x_proj (step-invariant, biases included) stored to a device scratch at t=0.
// O=2 linear head fused via per-warp shfl reduction.

#define NROWS   12800
#define HID     256
#define TSTEPS  16
#define MTILE   32
#define NTILES  400
#define THREADS 256
#define AP      264      // hx/cx row pitch (floats): multiple of 4 for float4 A loads
#define WP      258      // W-stage row pitch (floats): even for float2 B loads
#define KT      32       // k-tile
#define NKT     8        // 256 / 32

#define OFF_A    0
#define OFF_AN   (OFF_A   + MTILE*AP)     // 8448
#define OFF_CX   (OFF_AN  + MTILE*AP)     // 16896
#define OFF_WS0  (OFF_CX  + MTILE*AP)     // 25344
#define OFF_WS1  (OFF_WS0 + KT*WP)        // 33600
#define OFF_BIAS (OFF_WS1 + KT*WP)        // 41856
#define OFF_WLIN (OFF_BIAS + 1024)        // 42880
#define SMEM_FLOATS (OFF_WLIN + 512)      // 43392
#define SMEM_BYTES  (SMEM_FLOATS * 4)     // 173568 B -> 1 CTA/SM

// x_proj scratch: 12800 x 1024 fp32 = 52.4 MB (L2-resident on re-read)
__device__ float g_xproj[(size_t)NROWS * 1024];

__device__ __forceinline__ float fsig(float x) {
    return __fdividef(1.0f, 1.0f + __expf(-x));
}
__device__ __forceinline__ float ftanhx(float x) {
    return fmaf(2.0f, fsig(2.0f * x), -1.0f);
}
__device__ __forceinline__ void ffma2(unsigned long long &d,
                                      unsigned long long a,
                                      unsigned long long b) {
    asm("fma.rn.f32x2 %0, %1, %2, %0;" : "+l"(d) : "l"(a), "l"(b));
}
__device__ __forceinline__ unsigned long long pack2(float x) {
    unsigned long long r;
    unsigned u = __float_as_uint(x);
    asm("mov.b64 %0, {%1, %2};" : "=l"(r) : "r"(u), "r"(u));
    return r;
}

__global__ void __launch_bounds__(THREADS, 1)
lstm_fused(const float* __restrict__ x,
           const float* __restrict__ Wih, const float* __restrict__ Whh,
           const float* __restrict__ bih, const float* __restrict__ bhh,
           const float* __restrict__ Wlin, const float* __restrict__ blin,
           float* __restrict__ out)
{
    extern __shared__ float sm[];
    const int tid  = threadIdx.x;
    const int cg   = tid & 31;   // lane: hidden-col pair 2*cg
    const int rg   = tid >> 5;   // warp: rows rg*4 .. rg*4+3
    const int tile = blockIdx.x;
    const int n0   = tile * MTILE;

    for (int i = tid; i < 1024; i += THREADS) sm[OFF_BIAS + i] = bih[i] + bhh[i];
    for (int i = tid; i < 512;  i += THREADS) sm[OFF_WLIN + i] = Wlin[i];

    // Gather xf tile into A: A[r][c] = x[bb, c, hw0+r]  (1600 % 32 == 0: no b-crossing)
    {
        const int bb  = n0 / 1600;
        const int hw0 = n0 % 1600;
        const float* xb = x + (size_t)bb * (HID * 1600) + hw0;
        const int r  = tid & 31;
        const int c0 = tid >> 5;
        #pragma unroll
        for (int j = 0; j < 32; ++j) {
            int c = c0 + 8 * j;
            sm[OFF_A + r * AP + c] = xb[(size_t)c * 1600 + r];
        }
    }

    const float bl0 = blin[0], bl1 = blin[1];
    const int skq = tid & 7;     // staging: 16B chunk within k-tile
    const int sc0 = tid >> 3;    // staging: base column

    float* A  = sm + OFF_A;
    float* An = sm + OFF_AN;

    for (int t = 0; t < TSTEPS; ++t) {
        const float* Wm = (t == 0) ? Wih : Whh;   // both [1024, 256] row-major
        float y0a[4] = {0.f, 0.f, 0.f, 0.f};
        float y1a[4] = {0.f, 0.f, 0.f, 0.f};

        for (int p = 0; p < 4; ++p) {            // 64 hidden cols per pass
            float4 v[8];
            // prolog: stage k-tile 0 (fully coalesced 128B lines)
            #pragma unroll
            for (int s = 0; s < 8; ++s) {
                int c = sc0 + 32 * s;
                int grow = ((c >> 6) << 8) + (p << 6) + (c & 63);
                v[s] = *(const float4*)&Wm[(size_t)grow * HID + (skq << 2)];
            }
            __syncthreads();   // prev-pass readers of WS0 are done; also orders A/An swap
            {
                float* W0 = sm + OFF_WS0;
                #pragma unroll
                for (int s = 0; s < 8; ++s) {
                    int c = sc0 + 32 * s;
                    W0[(4 * skq + 0) * WP + c] = v[s].x;
                    W0[(4 * skq + 1) * WP + c] = v[s].y;
                    W0[(4 * skq + 2) * WP + c] = v[s].z;
                    W0[(4 * skq + 3) * WP + c] = v[s].w;
                }
            }
            __syncthreads();

            unsigned long long acc[4][4];   // [row i][gate g], f32x2 over col pair
            #pragma unroll
            for (int i = 0; i < 4; ++i)
                #pragma unroll
                for (int g = 0; g < 4; ++g) acc[i][g] = 0ull;

            for (int kt = 0; kt < NKT; ++kt) {
                if (kt < NKT - 1) {
                    #pragma unroll
                    for (int s = 0; s < 8; ++s) {
                        int c = sc0 + 32 * s;
                        int grow = ((c >> 6) << 8) + (p << 6) + (c & 63);
                        v[s] = *(const float4*)&Wm[(size_t)grow * HID + (kt + 1) * KT + (skq << 2)];
                    }
                }
                const float* Bs = sm + ((kt & 1) ? OFF_WS1 : OFF_WS0) + 2 * cg;
                #pragma unroll
                for (int k4 = 0; k4 < 8; ++k4) {
                    float4 af[4];
                    #pragma unroll
                    for (int i = 0; i < 4; ++i)
                        af[i] = *(const float4*)(A + (rg * 4 + i) * AP + kt * KT + k4 * 4);
                    #pragma unroll
                    for (int kk = 0; kk < 4; ++kk) {
                        int k = k4 * 4 + kk;
                        unsigned long long bq[4];
                        #pragma unroll
                        for (int g = 0; g < 4; ++g)
                            bq[g] = *(const unsigned long long*)(Bs + k * WP + g * 64);
                        #pragma unroll
                        for (int i = 0; i < 4; ++i) {
                            unsigned long long pa = pack2(((const float*)&af[i])[kk]);
                            #pragma unroll
                            for (int g = 0; g < 4; ++g) ffma2(acc[i][g], pa, bq[g]);
                        }
                    }
                }
                if (kt < NKT - 1) {
                    float* Wn = sm + (((kt + 1) & 1) ? OFF_WS1 : OFF_WS0);
                    #pragma unroll
                    for (int s = 0; s < 8; ++s) {
                        int c = sc0 + 32 * s;
                        Wn[(4 * skq + 0) * WP + c] = v[s].x;
                        Wn[(4 * skq + 1) * WP + c] = v[s].y;
                        Wn[(4 * skq + 2) * WP + c] = v[s].z;
                        Wn[(4 * skq + 3) * WP + c] = v[s].w;
                    }
                }
                __syncthreads();
            }

            // LSTM update for this pass's hidden cols {p*64+2cg, +1}
            const int colg = p * 64 + 2 * cg;
            const size_t xbase = (size_t)n0 * 1024;
            #pragma unroll
            for (int i = 0; i < 4; ++i) {
                int r = rg * 4 + i;
                float pre[4][2];
                if (t == 0) {
                    #pragma unroll
                    for (int g = 0; g < 4; ++g) {
                        float2 b2 = *(const float2*)&sm[OFF_BIAS + g * 256 + colg];
                        union { unsigned long long u; float2 f; } uu; uu.u = acc[i][g];
                        float2 pv; pv.x = uu.f.x + b2.x; pv.y = uu.f.y + b2.y;
                        pre[g][0] = pv.x; pre[g][1] = pv.y;
                        *(float2*)&g_xproj[xbase + (size_t)r * 1024 + g * 256 + colg] = pv;
                    }
                } else {
                    #pragma unroll
                    for (int g = 0; g < 4; ++g) {
                        float2 xp = *(const float2*)&g_xproj[xbase + (size_t)r * 1024 + g * 256 + colg];
                        union { unsigned long long u; float2 f; } uu; uu.u = acc[i][g];
                        pre[g][0] = uu.f.x + xp.x; pre[g][1] = uu.f.y + xp.y;
                    }
                }
                float2 cold;
                if (t == 0) { cold.x = 0.f; cold.y = 0.f; }
                else cold = *(const float2*)&sm[OFF_CX + r * AP + colg];

                float2 cnew, hnew;
                #pragma unroll
                for (int e = 0; e < 2; ++e) {
                    float ig = fsig(pre[0][e]);
                    float fg = fsig(pre[1][e]);
                    float gg = ftanhx(pre[2][e]);
                    float og = fsig(pre[3][e]);
                    float cp = e ? cold.y : cold.x;
                    float cn = fmaf(fg, cp, ig * gg);
                    float h  = og * ftanhx(cn);
                    if (e) { cnew.y = cn; hnew.y = h; } else { cnew.x = cn; hnew.x = h; }
                    float lh = (h > 0.f) ? h : 0.01f * h;
                    y0a[i] = fmaf(lh, sm[OFF_WLIN + colg + e],       y0a[i]);
                    y1a[i] = fmaf(lh, sm[OFF_WLIN + 256 + colg + e], y1a[i]);
                }
                *(float2*)&sm[OFF_CX + r * AP + colg] = cnew;
                *(float2*)&An[r * AP + colg] = hnew;
            }
        } // passes

        // Head: warp-reduce y over the 32 lanes (each warp owns 4 complete rows)
        #pragma unroll
        for (int i = 0; i < 4; ++i) {
            #pragma unroll
            for (int off = 16; off >= 1; off >>= 1) {
                y0a[i] += __shfl_xor_sync(0xffffffffu, y0a[i], off);
                y1a[i] += __shfl_xor_sync(0xffffffffu, y1a[i], off);
            }
        }
        if (cg < 8) {
            int i = cg >> 1, o = cg & 1;
            int n = n0 + rg * 4 + i;
            float val = (o ? y1a[i] : y0a[i]) + (o ? bl1 : bl0);
            out[((size_t)n * TSTEPS + t) * 2 + o] = val;
        }

        float* tmpp = A; A = An; An = tmpp;
    } // t
}

extern "C" void kernel_launch(void* const* d_in, const int* in_sizes, int n_in,
                              void* d_out, int out_size) {
    const float* x    = (const float*)d_in[0];
    // d_in[1] = hx (zeros), d_in[2] = cx (zeros) — folded into t==0 path
    const float* Wih  = (const float*)d_in[3];
    const float* Whh  = (const float*)d_in[4];
    const float* bih  = (const float*)d_in[5];
    const float* bhh  = (const float*)d_in[6];
    const float* Wlin = (const float*)d_in[7];
    const float* blin = (const float*)d_in[8];
    (void)in_sizes; (void)n_in; (void)out_size;

    cudaFuncSetAttribute(lstm_fused, cudaFuncAttributeMaxDynamicSharedMemorySize, SMEM_BYTES);
    lstm_fused<<<NTILES, THREADS, SMEM_BYTES>>>(x, Wih, Whh, bih, bhh, Wlin, blin,
                                                (float*)d_out);
}

// round 5
// speedup vs baseline: 1.0531x; 1.0531x over previous
#include <cuda_runtime.h>
#include <cuda_bf16.h>

// Fused persistent LSTM decoder (fp32, f32x2 FFMA), 8x8 register blocking.
// 400 CTAs x 256 threads; CTA owns 32 rows for all 16 steps. hx/cx in SMEM,
// W staged per 16-k tile into double-buffered SMEM (transpose, conflict-free),
// x_proj computed at t=0 (hx0=cx0=0) into device scratch, O=2 head fused.
// (Resubmission of R4 kernel — R4 bench was an infra failure, never measured.)

#define NROWS   12800
#define HID     256
#define TSTEPS  16
#define MTILE   32
#define NTILES  400
#define THREADS 256
#define AP      264            // hx/cx row pitch (floats)
#define SP      514            // W-stage k-row pitch (floats), conflict-free transpose
#define KT      16             // k-tile
#define NKT     16             // 256/16
#define NPASS   2              // 512 staged cols (4 gates x 128) per pass

#define OFF_A    0
#define OFF_AN   (OFF_A   + MTILE*AP)    // 8448
#define OFF_CX   (OFF_AN  + MTILE*AP)    // 16896
#define OFF_WS0  (OFF_CX  + MTILE*AP)    // 25344
#define OFF_WS1  (OFF_WS0 + KT*SP)       // 33568
#define OFF_BIAS (OFF_WS1 + KT*SP)       // 41792
#define OFF_WLIN (OFF_BIAS + 1024)       // 42816
#define OFF_HEAD (OFF_WLIN + 512)        // 43328
#define SMEM_FLOATS (OFF_HEAD + 128)     // 43456
#define SMEM_BYTES  (SMEM_FLOATS * 4)    // 173824 B -> 1 CTA/SM

typedef unsigned long long ull;

// x_proj scratch: 12800 x 1024 fp32 = 52.4 MB (L2-resident on re-read)
__device__ float g_xproj[(size_t)NROWS * 1024];

__device__ __forceinline__ float fsig(float x) {
    return __fdividef(1.0f, 1.0f + __expf(-x));
}
__device__ __forceinline__ float ftanhx(float x) {
    return fmaf(2.0f, fsig(2.0f * x), -1.0f);
}
__device__ __forceinline__ void ffma2(ull &d, ull a, ull b) {
    asm("fma.rn.f32x2 %0, %1, %2, %0;" : "+l"(d) : "l"(a), "l"(b));
}
__device__ __forceinline__ ull pack2(float x) {
    ull r;
    unsigned u = __float_as_uint(x);
    asm("mov.b64 %0, {%1, %2};" : "=l"(r) : "r"(u), "r"(u));
    return r;
}

__global__ void __launch_bounds__(THREADS, 1)
lstm_fused(const float* __restrict__ x,
           const float* __restrict__ Wih, const float* __restrict__ Whh,
           const float* __restrict__ bih, const float* __restrict__ bhh,
           const float* __restrict__ Wlin, const float* __restrict__ blin,
           float* __restrict__ out)
{
    extern __shared__ float sm[];
    const int tid  = threadIdx.x;
    const int ln   = tid & 31;
    const int w    = tid >> 5;
    const int rg   = w & 3;        // row group: rows rg*8 .. rg*8+7
    const int cgrp = w >> 2;       // col group 0/1 (64 cols per gate per pass)
    const int tile = blockIdx.x;
    const int n0   = tile * MTILE;

    for (int i = tid; i < 1024; i += THREADS) sm[OFF_BIAS + i] = bih[i] + bhh[i];
    for (int i = tid; i < 512;  i += THREADS) sm[OFF_WLIN + i] = Wlin[i];

    // Gather xf tile into A: A[r][c] = x[bb, c, hw0+r]   (1600 % 32 == 0)
    {
        const int bb  = n0 / 1600;
        const int hw0 = n0 % 1600;
        const float* xb = x + (size_t)bb * (HID * 1600) + hw0;
        const int r  = tid & 31;
        const int c0 = tid >> 5;
        #pragma unroll
        for (int j = 0; j < 32; ++j) {
            int c = c0 + 8 * j;
            sm[OFF_A + r * AP + c] = xb[(size_t)c * 1600 + r];
        }
    }

    const float bl0 = blin[0], bl1 = blin[1];
    const int skq = tid & 3;       // staging: 16B chunk within k-tile
    const int sc0 = tid >> 2;      // staging: base stage-col (0..63)

    float* A  = sm + OFF_A;
    float* An = sm + OFF_AN;

    #pragma unroll 1
    for (int t = 0; t < TSTEPS; ++t) {
        const float* Wm = (t == 0) ? Wih : Whh;   // [1024, 256] row-major
        float y0a[8], y1a[8];
        #pragma unroll
        for (int i = 0; i < 8; ++i) { y0a[i] = 0.f; y1a[i] = 0.f; }

        #pragma unroll 1
        for (int p = 0; p < NPASS; ++p) {
            float4 v[8];
            // prolog: prefetch k-tile 0 of this pass's 512 stage-cols
            #pragma unroll
            for (int it = 0; it < 8; ++it) {
                int s   = sc0 + 64 * it;                       // 0..511
                int orow = ((s >> 7) << 8) + (p << 7) + (s & 127);
                v[it] = *(const float4*)&Wm[(size_t)orow * HID + 4 * skq];
            }
            __syncthreads();   // prior readers of WS0 (and An writers) done
            {
                float* W0 = sm + OFF_WS0;
                #pragma unroll
                for (int it = 0; it < 8; ++it) {
                    int s = sc0 + 64 * it;
                    W0[(4 * skq + 0) * SP + s] = v[it].x;
                    W0[(4 * skq + 1) * SP + s] = v[it].y;
                    W0[(4 * skq + 2) * SP + s] = v[it].z;
                    W0[(4 * skq + 3) * SP + s] = v[it].w;
                }
            }
            __syncthreads();

            ull acc[8][4];
            #pragma unroll
            for (int i = 0; i < 8; ++i)
                #pragma unroll
                for (int g = 0; g < 4; ++g) acc[i][g] = 0ull;

            #pragma unroll 1
            for (int kt = 0; kt < NKT; ++kt) {
                if (kt < NKT - 1) {
                    #pragma unroll
                    for (int it = 0; it < 8; ++it) {
                        int s   = sc0 + 64 * it;
                        int orow = ((s >> 7) << 8) + (p << 7) + (s & 127);
                        v[it] = *(const float4*)&Wm[(size_t)orow * HID + (kt + 1) * KT + 4 * skq];
                    }
                }
                const float* Bs = sm + ((kt & 1) ? OFF_WS1 : OFF_WS0) + cgrp * 64 + 2 * ln;
                const float* Ar = A + rg * 8 * AP + kt * KT;
                #pragma unroll
                for (int k4 = 0; k4 < 4; ++k4) {
                    float4 af[8];
                    #pragma unroll
                    for (int i = 0; i < 8; ++i)
                        af[i] = *(const float4*)(Ar + i * AP + k4 * 4);
                    #pragma unroll
                    for (int kk = 0; kk < 4; ++kk) {
                        ull bq[4];
                        #pragma unroll
                        for (int g = 0; g < 4; ++g)
                            bq[g] = *(const ull*)(Bs + (k4 * 4 + kk) * SP + g * 128);
                        #pragma unroll
                        for (int i = 0; i < 8; ++i) {
                            ull pa = pack2(((const float*)&af[i])[kk]);
                            #pragma unroll
                            for (int g = 0; g < 4; ++g) ffma2(acc[i][g], pa, bq[g]);
                        }
                    }
                }
                if (kt < NKT - 1) {
                    float* Wn = sm + (((kt + 1) & 1) ? OFF_WS1 : OFF_WS0);
                    #pragma unroll
                    for (int it = 0; it < 8; ++it) {
                        int s = sc0 + 64 * it;
                        Wn[(4 * skq + 0) * SP + s] = v[it].x;
                        Wn[(4 * skq + 1) * SP + s] = v[it].y;
                        Wn[(4 * skq + 2) * SP + s] = v[it].z;
                        Wn[(4 * skq + 3) * SP + s] = v[it].w;
                    }
                }
                __syncthreads();
            }

            // LSTM update for hidden col pair {colg, colg+1}, rows rg*8..+7
            const int colg = p * 128 + cgrp * 64 + 2 * ln;
            #pragma unroll
            for (int i = 0; i < 8; ++i) {
                int r = rg * 8 + i;
                size_t xpo = (size_t)(n0 + r) * 1024 + colg;
                float pre[4][2];
                if (t == 0) {
                    #pragma unroll
                    for (int g = 0; g < 4; ++g) {
                        float2 b2 = *(const float2*)&sm[OFF_BIAS + g * 256 + colg];
                        union { ull u; float2 f; } uu; uu.u = acc[i][g];
                        float2 pv; pv.x = uu.f.x + b2.x; pv.y = uu.f.y + b2.y;
                        pre[g][0] = pv.x; pre[g][1] = pv.y;
                        *(float2*)&g_xproj[xpo + (size_t)g * 256] = pv;
                    }
                } else {
                    #pragma unroll
                    for (int g = 0; g < 4; ++g) {
                        float2 xp = *(const float2*)&g_xproj[xpo + (size_t)g * 256];
                        union { ull u; float2 f; } uu; uu.u = acc[i][g];
                        pre[g][0] = uu.f.x + xp.x; pre[g][1] = uu.f.y + xp.y;
                    }
                }
                float2 cold;
                if (t == 0) { cold.x = 0.f; cold.y = 0.f; }
                else cold = *(const float2*)&sm[OFF_CX + r * AP + colg];

                float2 cnew, hnew;
                #pragma unroll
                for (int e = 0; e < 2; ++e) {
                    float ig = fsig(pre[0][e]);
                    float fg = fsig(pre[1][e]);
                    float gg = ftanhx(pre[2][e]);
                    float og = fsig(pre[3][e]);
                    float cp = e ? cold.y : cold.x;
                    float cn = fmaf(fg, cp, ig * gg);
                    float h  = og * ftanhx(cn);
                    if (e) { cnew.y = cn; hnew.y = h; } else { cnew.x = cn; hnew.x = h; }
                    float lh = (h > 0.f) ? h : 0.01f * h;
                    y0a[i] = fmaf(lh, sm[OFF_WLIN + colg + e],       y0a[i]);
                    y1a[i] = fmaf(lh, sm[OFF_WLIN + 256 + colg + e], y1a[i]);
                }
                *(float2*)&sm[OFF_CX + r * AP + colg] = cnew;
                *(float2*)&An[r * AP + colg] = hnew;
            }
        } // passes

        // Head: butterfly over 32 lanes, combine the two col-group warps via SMEM
        #pragma unroll
        for (int i = 0; i < 8; ++i) {
            #pragma unroll
            for (int off = 16; off >= 1; off >>= 1) {
                y0a[i] += __shfl_xor_sync(0xffffffffu, y0a[i], off);
                y1a[i] += __shfl_xor_sync(0xffffffffu, y1a[i], off);
            }
        }
        if (ln < 8)       sm[OFF_HEAD + (rg * 8 + ln) * 4 + cgrp * 2 + 0] = y0a[ln];
        else if (ln < 16) sm[OFF_HEAD + (rg * 8 + ln - 8) * 4 + cgrp * 2 + 1] = y1a[ln - 8];
        __syncthreads();
        if (tid < 64) {
            int r = tid >> 1, o = tid & 1;
            float val = sm[OFF_HEAD + r * 4 + o] + sm[OFF_HEAD + r * 4 + 2 + o]
                      + (o ? bl1 : bl0);
            out[(size_t)(n0 + r) * (TSTEPS * 2) + t * 2 + o] = val;
        }

        float* tmpp = A; A = An; An = tmpp;
    } // t
}

extern "C" void kernel_launch(void* const* d_in, const int* in_sizes, int n_in,
                              void* d_out, int out_size) {
    const float* x    = (const float*)d_in[0];
    // d_in[1]=hx(zeros), d_in[2]=cx(zeros) folded into t==0 path
    const float* Wih  = (const float*)d_in[3];
    const float* Whh  = (const float*)d_in[4];
    const float* bih  = (const float*)d_in[5];
    const float* bhh  = (const float*)d_in[6];
    const float* Wlin = (const float*)d_in[7];
    const float* blin = (const float*)d_in[8];
    (void)in_sizes; (void)n_in; (void)out_size;

    cudaFuncSetAttribute(lstm_fused, cudaFuncAttributeMaxDynamicSharedMemorySize, SMEM_BYTES);
    lstm_fused<<<NTILES, THREADS, SMEM_BYTES>>>(x, Wih, Whh, bih, bhh, Wlin, blin,
                                                (float*)d_out);
}

// round 6
// speedup vs baseline: 1.0537x; 1.0005x over previous
#include <cuda_runtime.h>
#include <cuda_bf16.h>

// Fused persistent LSTM decoder (fp32, f32x2 FFMA), 8x8 register blocking.
// 400 CTAs x 256 threads; CTA owns 32 rows for all 16 steps. hx/cx in SMEM,
// W staged per 16-k tile into double-buffered SMEM (transpose, conflict-free),
// x_proj computed at t=0 (hx0=cx0=0) into device scratch, O=2 head fused.
// (Resubmission of R4 kernel — R4 bench was an infra failure, never measured.)

#define NROWS   12800
#define HID     256
#define TSTEPS  16
#define MTILE   32
#define NTILES  400
#define THREADS 256
#define AP      264            // hx/cx row pitch (floats)
#define SP      514            // W-stage k-row pitch (floats), conflict-free transpose
#define KT      16             // k-tile
#define NKT     16             // 256/16
#define NPASS   2              // 512 staged cols (4 gates x 128) per pass

#define OFF_A    0
#define OFF_AN   (OFF_A   + MTILE*AP)    // 8448
#define OFF_CX   (OFF_AN  + MTILE*AP)    // 16896
#define OFF_WS0  (OFF_CX  + MTILE*AP)    // 25344
#define OFF_WS1  (OFF_WS0 + KT*SP)       // 33568
#define OFF_BIAS (OFF_WS1 + KT*SP)       // 41792
#define OFF_WLIN (OFF_BIAS + 1024)       // 42816
#define OFF_HEAD (OFF_WLIN + 512)        // 43328
#define SMEM_FLOATS (OFF_HEAD + 128)     // 43456
#define SMEM_BYTES  (SMEM_FLOATS * 4)    // 173824 B -> 1 CTA/SM

typedef unsigned long long ull;

// x_proj scratch: 12800 x 1024 fp32 = 52.4 MB (L2-resident on re-read)
__device__ float g_xproj[(size_t)NROWS * 1024];

__device__ __forceinline__ float fsig(float x) {
    return __fdividef(1.0f, 1.0f + __expf(-x));
}
__device__ __forceinline__ float ftanhx(float x) {
    return fmaf(2.0f, fsig(2.0f * x), -1.0f);
}
__device__ __forceinline__ void ffma2(ull &d, ull a, ull b) {
    asm("fma.rn.f32x2 %0, %1, %2, %0;" : "+l"(d) : "l"(a), "l"(b));
}
__device__ __forceinline__ ull pack2(float x) {
    ull r;
    unsigned u = __float_as_uint(x);
    asm("mov.b64 %0, {%1, %2};" : "=l"(r) : "r"(u), "r"(u));
    return r;
}

__global__ void __launch_bounds__(THREADS, 1)
lstm_fused(const float* __restrict__ x,
           const float* __restrict__ Wih, const float* __restrict__ Whh,
           const float* __restrict__ bih, const float* __restrict__ bhh,
           const float* __restrict__ Wlin, const float* __restrict__ blin,
           float* __restrict__ out)
{
    extern __shared__ float sm[];
    const int tid  = threadIdx.x;
    const int ln   = tid & 31;
    const int w    = tid >> 5;
    const int rg   = w & 3;        // row group: rows rg*8 .. rg*8+7
    const int cgrp = w >> 2;       // col group 0/1 (64 cols per gate per pass)
    const int tile = blockIdx.x;
    const int n0   = tile * MTILE;

    for (int i = tid; i < 1024; i += THREADS) sm[OFF_BIAS + i] = bih[i] + bhh[i];
    for (int i = tid; i < 512;  i += THREADS) sm[OFF_WLIN + i] = Wlin[i];

    // Gather xf tile into A: A[r][c] = x[bb, c, hw0+r]   (1600 % 32 == 0)
    {
        const int bb  = n0 / 1600;
        const int hw0 = n0 % 1600;
        const float* xb = x + (size_t)bb * (HID * 1600) + hw0;
        const int r  = tid & 31;
        const int c0 = tid >> 5;
        #pragma unroll
        for (int j = 0; j < 32; ++j) {
            int c = c0 + 8 * j;
            sm[OFF_A + r * AP + c] = xb[(size_t)c * 1600 + r];
        }
    }

    const float bl0 = blin[0], bl1 = blin[1];
    const int skq = tid & 3;       // staging: 16B chunk within k-tile
    const int sc0 = tid >> 2;      // staging: base stage-col (0..63)

    float* A  = sm + OFF_A;
    float* An = sm + OFF_AN;

    #pragma unroll 1
    for (int t = 0; t < TSTEPS; ++t) {
        const float* Wm = (t == 0) ? Wih : Whh;   // [1024, 256] row-major
        float y0a[8], y1a[8];
        #pragma unroll
        for (int i = 0; i < 8; ++i) { y0a[i] = 0.f; y1a[i] = 0.f; }

        #pragma unroll 1
        for (int p = 0; p < NPASS; ++p) {
            float4 v[8];
            // prolog: prefetch k-tile 0 of this pass's 512 stage-cols
            #pragma unroll
            for (int it = 0; it < 8; ++it) {
                int s   = sc0 + 64 * it;                       // 0..511
                int orow = ((s >> 7) << 8) + (p << 7) + (s & 127);
                v[it] = *(const float4*)&Wm[(size_t)orow * HID + 4 * skq];
            }
            __syncthreads();   // prior readers of WS0 (and An writers) done
            {
                float* W0 = sm + OFF_WS0;
                #pragma unroll
                for (int it = 0; it < 8; ++it) {
                    int s = sc0 + 64 * it;
                    W0[(4 * skq + 0) * SP + s] = v[it].x;
                    W0[(4 * skq + 1) * SP + s] = v[it].y;
                    W0[(4 * skq + 2) * SP + s] = v[it].z;
                    W0[(4 * skq + 3) * SP + s] = v[it].w;
                }
            }
            __syncthreads();

            ull acc[8][4];
            #pragma unroll
            for (int i = 0; i < 8; ++i)
                #pragma unroll
                for (int g = 0; g < 4; ++g) acc[i][g] = 0ull;

            #pragma unroll 1
            for (int kt = 0; kt < NKT; ++kt) {
                if (kt < NKT - 1) {
                    #pragma unroll
                    for (int it = 0; it < 8; ++it) {
                        int s   = sc0 + 64 * it;
                        int orow = ((s >> 7) << 8) + (p << 7) + (s & 127);
                        v[it] = *(const float4*)&Wm[(size_t)orow * HID + (kt + 1) * KT + 4 * skq];
                    }
                }
                const float* Bs = sm + ((kt & 1) ? OFF_WS1 : OFF_WS0) + cgrp * 64 + 2 * ln;
                const float* Ar = A + rg * 8 * AP + kt * KT;
                #pragma unroll
                for (int k4 = 0; k4 < 4; ++k4) {
                    float4 af[8];
                    #pragma unroll
                    for (int i = 0; i < 8; ++i)
                        af[i] = *(const float4*)(Ar + i * AP + k4 * 4);
                    #pragma unroll
                    for (int kk = 0; kk < 4; ++kk) {
                        ull bq[4];
                        #pragma unroll
                        for (int g = 0; g < 4; ++g)
                            bq[g] = *(const ull*)(Bs + (k4 * 4 + kk) * SP + g * 128);
                        #pragma unroll
                        for (int i = 0; i < 8; ++i) {
                            ull pa = pack2(((const float*)&af[i])[kk]);
                            #pragma unroll
                            for (int g = 0; g < 4; ++g) ffma2(acc[i][g], pa, bq[g]);
                        }
                    }
                }
                if (kt < NKT - 1) {
                    float* Wn = sm + (((kt + 1) & 1) ? OFF_WS1 : OFF_WS0);
                    #pragma unroll
                    for (int it = 0; it < 8; ++it) {
                        int s = sc0 + 64 * it;
                        Wn[(4 * skq + 0) * SP + s] = v[it].x;
                        Wn[(4 * skq + 1) * SP + s] = v[it].y;
                        Wn[(4 * skq + 2) * SP + s] = v[it].z;
                        Wn[(4 * skq + 3) * SP + s] = v[it].w;
                    }
                }
                __syncthreads();
            }

            // LSTM update for hidden col pair {colg, colg+1}, rows rg*8..+7
            const int colg = p * 128 + cgrp * 64 + 2 * ln;
            #pragma unroll
            for (int i = 0; i < 8; ++i) {
                int r = rg * 8 + i;
                size_t xpo = (size_t)(n0 + r) * 1024 + colg;
                float pre[4][2];
                if (t == 0) {
                    #pragma unroll
                    for (int g = 0; g < 4; ++g) {
                        float2 b2 = *(const float2*)&sm[OFF_BIAS + g * 256 + colg];
                        union { ull u; float2 f; } uu; uu.u = acc[i][g];
                        float2 pv; pv.x = uu.f.x + b2.x; pv.y = uu.f.y + b2.y;
                        pre[g][0] = pv.x; pre[g][1] = pv.y;
                        *(float2*)&g_xproj[xpo + (size_t)g * 256] = pv;
                    }
                } else {
                    #pragma unroll
                    for (int g = 0; g < 4; ++g) {
                        float2 xp = *(const float2*)&g_xproj[xpo + (size_t)g * 256];
                        union { ull u; float2 f; } uu; uu.u = acc[i][g];
                        pre[g][0] = uu.f.x + xp.x; pre[g][1] = uu.f.y + xp.y;
                    }
                }
                float2 cold;
                if (t == 0) { cold.x = 0.f; cold.y = 0.f; }
                else cold = *(const float2*)&sm[OFF_CX + r * AP + colg];

                float2 cnew, hnew;
                #pragma unroll
                for (int e = 0; e < 2; ++e) {
                    float ig = fsig(pre[0][e]);
                    float fg = fsig(pre[1][e]);
                    float gg = ftanhx(pre[2][e]);
                    float og = fsig(pre[3][e]);
                    float cp = e ? cold.y : cold.x;
                    float cn = fmaf(fg, cp, ig * gg);
                    float h  = og * ftanhx(cn);
                    if (e) { cnew.y = cn; hnew.y = h; } else { cnew.x = cn; hnew.x = h; }
                    float lh = (h > 0.f) ? h : 0.01f * h;
                    y0a[i] = fmaf(lh, sm[OFF_WLIN + colg + e],       y0a[i]);
                    y1a[i] = fmaf(lh, sm[OFF_WLIN + 256 + colg + e], y1a[i]);
                }
                *(float2*)&sm[OFF_CX + r * AP + colg] = cnew;
                *(float2*)&An[r * AP + colg] = hnew;
            }
        } // passes

        // Head: butterfly over 32 lanes, combine the two col-group warps via SMEM
        #pragma unroll
        for (int i = 0; i < 8; ++i) {
            #pragma unroll
            for (int off = 16; off >= 1; off >>= 1) {
                y0a[i] += __shfl_xor_sync(0xffffffffu, y0a[i], off);
                y1a[i] += __shfl_xor_sync(0xffffffffu, y1a[i], off);
            }
        }
        if (ln < 8)       sm[OFF_HEAD + (rg * 8 + ln) * 4 + cgrp * 2 + 0] = y0a[ln];
        else if (ln < 16) sm[OFF_HEAD + (rg * 8 + ln - 8) * 4 + cgrp * 2 + 1] = y1a[ln - 8];
        __syncthreads();
        if (tid < 64) {
            int r = tid >> 1, o = tid & 1;
            float val = sm[OFF_HEAD + r * 4 + o] + sm[OFF_HEAD + r * 4 + 2 + o]
                      + (o ? bl1 : bl0);
            out[(size_t)(n0 + r) * (TSTEPS * 2) + t * 2 + o] = val;
        }

        float* tmpp = A; A = An; An = tmpp;
    } // t
}

extern "C" void kernel_launch(void* const* d_in, const int* in_sizes, int n_in,
                              void* d_out, int out_size) {
    const float* x    = (const float*)d_in[0];
    // d_in[1]=hx(zeros), d_in[2]=cx(zeros) folded into t==0 path
    const float* Wih  = (const float*)d_in[3];
    const float* Whh  = (const float*)d_in[4];
    const float* bih  = (const float*)d_in[5];
    const float* bhh  = (const float*)d_in[6];
    const float* Wlin = (const float*)d_in[7];
    const float* blin = (const float*)d_in[8];
    (void)in_sizes; (void)n_in; (void)out_size;

    cudaFuncSetAttribute(lstm_fused, cudaFuncAttributeMaxDynamicSharedMemorySize, SMEM_BYTES);
    lstm_fused<<<NTILES, THREADS, SMEM_BYTES>>>(x, Wih, Whh, bih, bhh, Wlin, blin,
                                                (float*)d_out);
}